// round 14
// baseline (speedup 1.0000x reference)
#include <cuda_runtime.h>
#include <cuda_fp16.h>
#include <cstdint>

// ---------------------------------------------------------------------------
// Fused sparse-conv block, single-pass fp16 (x and W fp16, fp32 acc).
// R14 = R13 with the buffer-init bug fixed (R13 zeroed only half of each
// warp buffer -> garbage in rows 16-31; rel_err 45).
// Fully sparse warp staging: one lane per row; ballot row-valid masks;
// per active tap only valid rows cp.async'd, only previous tenants re-zeroed.
// Warp-autonomous active-tap loop, frag-ordered B LDG.128, 2 CTAs/SM.
// CTA tile: M=128 x N=64, 8 warps (32x32 tiles).
// ---------------------------------------------------------------------------

typedef __half fp16;
#define N_CH 64
#define MAXP 250048

__device__ fp16  g_x16[(size_t)MAXP * N_CH];
__device__ fp16  g_a16[(size_t)MAXP * N_CH];
__device__ fp16  g_b16[(size_t)MAXP * N_CH];
__device__ uint4 g_wf[4 * 27 * 16 * 32];       // frag-ordered weights

// ---- smem layout ----
#define OFF_BIAS  0                    // 64 floats = 256
#define OFF_NBS   256                  // 128*27 ints = 13824 -> 14080
#define OFF_WBUF  14336                // 8 warps * 2 bufs * 4096B
#define SMEM_TOTAL (OFF_WBUF + 8 * 2 * 4096)   // 79872 -> 2 CTAs/SM

// ---------------- PTX helpers ----------------
__device__ __forceinline__ void cp16b(void* dst, const void* src) {
    uint32_t d;
    asm("{ .reg .u64 t; cvta.to.shared.u64 t, %1; cvt.u32.u64 %0, t; }" : "=r"(d) : "l"(dst));
    asm volatile("cp.async.ca.shared.global [%0], [%1], 16;" :: "r"(d), "l"(src));
}
__device__ __forceinline__ void zero16(void* dst) {
    *(float4*)dst = make_float4(0.f, 0.f, 0.f, 0.f);
}
#define CP_COMMIT() asm volatile("cp.async.commit_group;" ::: "memory")
#define CP_WAIT1()  asm volatile("cp.async.wait_group 1;" ::: "memory")
#define CP_WAIT0()  asm volatile("cp.async.wait_group 0;" ::: "memory")

__device__ __forceinline__ void ldsm4(uint32_t* r, uint32_t addr) {
    asm volatile("ldmatrix.sync.aligned.m8n8.x4.shared.b16 {%0,%1,%2,%3}, [%4];"
                 : "=r"(r[0]), "=r"(r[1]), "=r"(r[2]), "=r"(r[3]) : "r"(addr));
}
__device__ __forceinline__ void mma_fp16(float* c, const uint32_t* a,
                                         uint32_t b0, uint32_t b1) {
    asm volatile(
        "mma.sync.aligned.m16n8k16.row.col.f32.f16.f16.f32 "
        "{%0,%1,%2,%3}, {%4,%5,%6,%7}, {%8,%9}, {%0,%1,%2,%3};"
        : "+f"(c[0]), "+f"(c[1]), "+f"(c[2]), "+f"(c[3])
        : "r"(a[0]), "r"(a[1]), "r"(a[2]), "r"(a[3]), "r"(b0), "r"(b1));
}

// ---------------- prep kernels ----------------
__global__ void prep_weights(const float* __restrict__ W0, const float* __restrict__ W1,
                             const float* __restrict__ W2, const float* __restrict__ W3,
                             uint4* __restrict__ wf) {
    int idx = blockIdx.x * 256 + threadIdx.x;    // over 4*27*16*32 = 55296
    if (idx >= 4 * 27 * 16 * 32) return;
    int lane  = idx & 31;
    int blk   = (idx >> 5) & 15;
    int k     = (idx >> 9) % 27;
    int layer = idx / (27 * 512);
    int wx = blk >> 3, kspair = (blk >> 2) & 1, g = blk & 3;
    int n   = wx * 32 + g * 8 + (lane >> 2);
    int kk0 = kspair * 32 + 2 * (lane & 3);
    const float* W = (layer == 0) ? W0 : (layer == 1) ? W1 : (layer == 2) ? W2 : W3;
    auto pack = [&](int kk) -> uint32_t {
        __half h0 = __float2half(W[((size_t)k * 64 + kk) * 64 + n]);
        __half h1 = __float2half(W[((size_t)k * 64 + kk + 1) * 64 + n]);
        return (uint32_t)__half_as_ushort(h0) | ((uint32_t)__half_as_ushort(h1) << 16);
    };
    uint4 v;
    v.x = pack(kk0); v.y = pack(kk0 + 8); v.z = pack(kk0 + 16); v.w = pack(kk0 + 24);
    wf[idx] = v;
}

__global__ void prep_feats(const float* __restrict__ f, fp16* __restrict__ x16, int n) {
    int i = blockIdx.x * 256 + threadIdx.x;
    if (i >= n) return;
    x16[i] = __float2half(f[i]);
}

// ---------------- main conv kernel ----------------
// MODE 0: relu(acc+b) -> fp16 | MODE 1: (acc+b)*beta+gamma -> fp16 (extra=cond)
// MODE 3: relu(acc+b)+extra -> fp32 (extra=feats)
template <int MODE>
__global__ __launch_bounds__(256, 2) void conv_mma(
    const fp16* __restrict__ x,
    const int*  __restrict__ nbr,
    const uint4* __restrict__ wf,
    const float* __restrict__ bias, const float* __restrict__ extra,
    float* __restrict__ outf, fp16* __restrict__ out16,
    int P)
{
    extern __shared__ char smem[];
    const uint32_t sb = (uint32_t)__cvta_generic_to_shared(smem);
    const int tid  = threadIdx.x;
    const int wid  = tid >> 5;
    const int lane = tid & 31;
    const int wy   = wid >> 1;        // 0..3 : 32-row slab
    const int wx   = wid & 1;         // 0..1 : 32-col half
    const int rA   = lane >> 2;
    const int cq   = lane & 3;
    const int p0   = blockIdx.x * 128;

    int*   nbs     = (int*)(smem + OFF_NBS);
    float* bias_sm = (float*)(smem + OFF_BIAS);

    // ---- prologue: bias + neighbor table (ONE CTA barrier) ----
    if (tid < 64) bias_sm[tid] = bias[tid];
    for (int t = tid; t < 128 * 27; t += 256) {
        int row = t / 27, p = p0 + row;
        nbs[t] = (p < P) ? nbr[(size_t)p * 27 + (t - row * 27)] : -1;
    }
    __syncthreads();

    // ---- per-warp active-tap mask: lane owns row wy*32+lane ----
    const int myrow = wy * 32 + lane;
    uint32_t rowtaps = 0;
    #pragma unroll
    for (int k = 0; k < 27; ++k)
        rowtaps |= (nbs[myrow * 27 + k] >= 0) ? (1u << k) : 0u;
    uint32_t wmask = rowtaps;
    #pragma unroll
    for (int o = 16; o; o >>= 1) wmask |= __shfl_xor_sync(0xffffffffu, wmask, o);

    float acc[2][4][4];
    #pragma unroll
    for (int t = 0; t < 2; ++t)
        #pragma unroll
        for (int j = 0; j < 4; ++j)
            #pragma unroll
            for (int q = 0; q < 4; ++q) acc[t][j][q] = 0.f;

    // ---- warp-private double buffer: zero FULLY once (8192B = 16 chunks/lane)
    char* wbuf0 = smem + OFF_WBUF + wid * 8192;
    #pragma unroll
    for (int i = 0; i < 16; ++i)
        zero16(wbuf0 + (i * 32 + lane) * 16);

    uint32_t tenant0 = 0u, tenant1 = 0u;   // rows currently non-zero per buffer
    uint32_t vm0 = 0u, vm1 = 0u;           // row-valid mask of staged tap

    const uint32_t mybit = 1u << lane;

    // sparse stage: lane handles its own row only. buf selected by caller.
    auto stage = [&](int k, int buf) {
        const int n = nbs[myrow * 27 + k];
        const uint32_t newm = __ballot_sync(0xffffffffu, n >= 0);
        const uint32_t ten  = buf ? tenant1 : tenant0;
        char* dst = wbuf0 + buf * 4096 + lane * 128;
        if (n >= 0) {
            const fp16* src = x + (size_t)n * 64;
            #pragma unroll
            for (int c = 0; c < 8; ++c)
                cp16b(dst + ((c ^ (lane & 7)) << 4), src + c * 8);
        } else if (ten & mybit) {
            #pragma unroll
            for (int c = 0; c < 8; ++c)
                zero16(dst + (c << 4));    // XOR-swizzle is a row-local bijection
        }
        CP_COMMIT();
        if (buf) { tenant1 = newm; vm1 = newm; }
        else     { tenant0 = newm; vm0 = newm; }
    };

    // ldmatrix A mapping (warp-local rows 0..31)
    const int mm = lane >> 3;
    const int r8 = lane & 7;
    const int arow0 = (mm & 1) * 8 + r8;
    const int akc   = mm >> 1;

    const uint4* wbase = wf + ((size_t)wx * 8) * 32 + lane;

    auto compute = [&](int k, int buf) {
        const uint32_t vm = buf ? vm1 : vm0;
        const bool act0 = (vm & 0x0000FFFFu) != 0;
        const bool act1 = (vm & 0xFFFF0000u) != 0;
        const uint32_t stg = sb + OFF_WBUF + (uint32_t)(wid * 8192 + buf * 4096);
        const uint4* wp = wbase + (size_t)k * 16 * 32;

        #pragma unroll
        for (int kp = 0; kp < 2; ++kp) {
            uint4 bv[4];
            #pragma unroll
            for (int i = 0; i < 4; ++i) bv[i] = wp[(kp * 4 + i) * 32];
            #pragma unroll
            for (int par = 0; par < 2; ++par) {
                const int ca = (kp * 2 + par) * 2 + akc;
                uint32_t a[2][4];
                #pragma unroll
                for (int t = 0; t < 2; ++t) {
                    if (t == 0 ? act0 : act1) {
                        const int row = arow0 + t * 16;
                        const uint32_t off =
                            (uint32_t)(row * 128 + (((uint32_t)ca ^ (row & 7)) << 4));
                        ldsm4(a[t], stg + off);
                    }
                }
                #pragma unroll
                for (int t = 0; t < 2; ++t) {
                    if (t == 0 ? !act0 : !act1) continue;
                    #pragma unroll
                    for (int j = 0; j < 4; ++j) {
                        if (par == 0) mma_fp16(acc[t][j], a[t], bv[j].x, bv[j].y);
                        else          mma_fp16(acc[t][j], a[t], bv[j].z, bv[j].w);
                    }
                }
            }
        }
    };

    // ---- warp-autonomous mainloop over active taps (no CTA barriers) ----
    if (wmask) {
        uint32_t m = wmask;
        int k = __ffs(m) - 1; m &= m - 1;
        int buf = 0;
        stage(k, 0);
        while (m) {
            int kn = __ffs(m) - 1; m &= m - 1;
            stage(kn, buf ^ 1);
            CP_WAIT1();
            __syncwarp();
            compute(k, buf);
            k = kn; buf ^= 1;
        }
        CP_WAIT0();
        __syncwarp();
        compute(k, buf);
    }

    // ---------------- epilogue ----------------
    #pragma unroll
    for (int t = 0; t < 2; ++t) {
        #pragma unroll
        for (int half = 0; half < 2; ++half) {
            const int p = p0 + wy * 32 + t * 16 + rA + half * 8;
            if (p >= P) continue;
            #pragma unroll
            for (int j = 0; j < 4; ++j) {
                const int col = wx * 32 + j * 8 + cq * 2;
                float v0 = acc[t][j][half * 2 + 0] + bias_sm[col];
                float v1 = acc[t][j][half * 2 + 1] + bias_sm[col + 1];
                if (MODE == 0) {
                    v0 = fmaxf(v0, 0.f); v1 = fmaxf(v1, 0.f);
                } else if (MODE == 1) {
                    float2 be = *(const float2*)(extra + (size_t)p * 128 + col);
                    float2 ga = *(const float2*)(extra + (size_t)p * 128 + 64 + col);
                    v0 = v0 * be.x + ga.x;
                    v1 = v1 * be.y + ga.y;
                } else {
                    float2 rs = *(const float2*)(extra + (size_t)p * 64 + col);
                    v0 = fmaxf(v0, 0.f) + rs.x;
                    v1 = fmaxf(v1, 0.f) + rs.y;
                }
                if (MODE == 3) {
                    *(float2*)(outf + (size_t)p * 64 + col) = make_float2(v0, v1);
                } else {
                    __half2 hv = __floats2half2_rn(v0, v1);
                    *(__half2*)(out16 + (size_t)p * 64 + col) = hv;
                }
            }
        }
    }
}

// ---------------- launch ----------------
extern "C" void kernel_launch(void* const* d_in, const int* in_sizes, int n_in,
                              void* d_out, int out_size)
{
    const float* feats = (const float*)d_in[0];
    const float* cond  = (const float*)d_in[1];
    const float* W1a   = (const float*)d_in[2];
    const float* b1a   = (const float*)d_in[3];
    const float* W1b   = (const float*)d_in[4];
    const float* b1b   = (const float*)d_in[5];
    const float* W2a   = (const float*)d_in[6];
    const float* b2a   = (const float*)d_in[7];
    const float* W2b   = (const float*)d_in[8];
    const float* b2b   = (const float*)d_in[9];
    const int*   nbr   = (const int*)d_in[10];

    int P = in_sizes[0] / N_CH;
    float* out = (float*)d_out;

    fp16 *x16, *a16, *b16;
    uint4* wf;
    cudaGetSymbolAddress((void**)&x16, g_x16);
    cudaGetSymbolAddress((void**)&a16, g_a16);
    cudaGetSymbolAddress((void**)&b16, g_b16);
    cudaGetSymbolAddress((void**)&wf,  g_wf);

    cudaFuncSetAttribute(conv_mma<0>, cudaFuncAttributeMaxDynamicSharedMemorySize, SMEM_TOTAL);
    cudaFuncSetAttribute(conv_mma<1>, cudaFuncAttributeMaxDynamicSharedMemorySize, SMEM_TOTAL);
    cudaFuncSetAttribute(conv_mma<3>, cudaFuncAttributeMaxDynamicSharedMemorySize, SMEM_TOTAL);

    prep_weights<<<(4 * 27 * 16 * 32 + 255) / 256, 256>>>(W1a, W1b, W2a, W2b, wf);
    prep_feats<<<(P * N_CH + 255) / 256, 256>>>(feats, x16, P * N_CH);

    const size_t LW = (size_t)27 * 16 * 32;
    int grid = (P + 127) / 128;
    conv_mma<0><<<grid, 256, SMEM_TOTAL>>>(x16, nbr, wf + 0 * LW,
                                           b1a, nullptr, nullptr, a16, P);
    conv_mma<1><<<grid, 256, SMEM_TOTAL>>>(a16, nbr, wf + 1 * LW,
                                           b1b, cond, nullptr, b16, P);
    conv_mma<0><<<grid, 256, SMEM_TOTAL>>>(b16, nbr, wf + 2 * LW,
                                           b2a, nullptr, nullptr, a16, P);
    conv_mma<3><<<grid, 256, SMEM_TOTAL>>>(a16, nbr, wf + 3 * LW,
                                           b2b, feats, out, nullptr, P);
}

// round 15
// speedup vs baseline: 1.1517x; 1.1517x over previous
#include <cuda_runtime.h>
#include <cuda_fp16.h>
#include <cstdint>

// ---------------------------------------------------------------------------
// Fused sparse-conv block, single-pass fp16 (x and W fp16, fp32 acc).
// R15: latency-chain attack on the warp-autonomous skeleton (R12/R14):
//  - NO smem neighbor table, NO CTA barriers: per-lane local nbr[27] array
//  - 3-deep warp-private cp.async ring (stage 2 taps ahead), statically
//    unrolled so tenant/valid masks stay in registers
//  - full-tap bv[8] LDG.128 burst (max B MLP)
//  - sparse ballot staging (only valid rows copied, only ex-tenants re-zeroed)
// CTA tile: M=128 x N=64, 8 warps (32x32), 2 CTAs/SM, 96KB smem.
// ---------------------------------------------------------------------------

typedef __half fp16;
#define N_CH 64
#define MAXP 250048

__device__ fp16  g_x16[(size_t)MAXP * N_CH];
__device__ fp16  g_a16[(size_t)MAXP * N_CH];
__device__ fp16  g_b16[(size_t)MAXP * N_CH];
__device__ uint4 g_wf[4 * 27 * 16 * 32];       // frag-ordered weights

#define SMEM_TOTAL (8 * 3 * 4096)              // 98304 -> 2 CTAs/SM

// ---------------- PTX helpers ----------------
__device__ __forceinline__ void cp16b(void* dst, const void* src) {
    uint32_t d;
    asm("{ .reg .u64 t; cvta.to.shared.u64 t, %1; cvt.u32.u64 %0, t; }" : "=r"(d) : "l"(dst));
    asm volatile("cp.async.ca.shared.global [%0], [%1], 16;" :: "r"(d), "l"(src));
}
__device__ __forceinline__ void zero16(void* dst) {
    *(float4*)dst = make_float4(0.f, 0.f, 0.f, 0.f);
}
#define CP_COMMIT() asm volatile("cp.async.commit_group;" ::: "memory")
#define CP_WAIT2()  asm volatile("cp.async.wait_group 2;" ::: "memory")
#define CP_WAIT0()  asm volatile("cp.async.wait_group 0;" ::: "memory")

__device__ __forceinline__ void ldsm4(uint32_t* r, uint32_t addr) {
    asm volatile("ldmatrix.sync.aligned.m8n8.x4.shared.b16 {%0,%1,%2,%3}, [%4];"
                 : "=r"(r[0]), "=r"(r[1]), "=r"(r[2]), "=r"(r[3]) : "r"(addr));
}
__device__ __forceinline__ void mma_fp16(float* c, const uint32_t* a,
                                         uint32_t b0, uint32_t b1) {
    asm volatile(
        "mma.sync.aligned.m16n8k16.row.col.f32.f16.f16.f32 "
        "{%0,%1,%2,%3}, {%4,%5,%6,%7}, {%8,%9}, {%0,%1,%2,%3};"
        : "+f"(c[0]), "+f"(c[1]), "+f"(c[2]), "+f"(c[3])
        : "r"(a[0]), "r"(a[1]), "r"(a[2]), "r"(a[3]), "r"(b0), "r"(b1));
}

// ---------------- prep kernels ----------------
__global__ void prep_weights(const float* __restrict__ W0, const float* __restrict__ W1,
                             const float* __restrict__ W2, const float* __restrict__ W3,
                             uint4* __restrict__ wf) {
    int idx = blockIdx.x * 256 + threadIdx.x;    // over 4*27*16*32 = 55296
    if (idx >= 4 * 27 * 16 * 32) return;
    int lane  = idx & 31;
    int blk   = (idx >> 5) & 15;
    int k     = (idx >> 9) % 27;
    int layer = idx / (27 * 512);
    int wx = blk >> 3, kspair = (blk >> 2) & 1, g = blk & 3;
    int n   = wx * 32 + g * 8 + (lane >> 2);
    int kk0 = kspair * 32 + 2 * (lane & 3);
    const float* W = (layer == 0) ? W0 : (layer == 1) ? W1 : (layer == 2) ? W2 : W3;
    auto pack = [&](int kk) -> uint32_t {
        __half h0 = __float2half(W[((size_t)k * 64 + kk) * 64 + n]);
        __half h1 = __float2half(W[((size_t)k * 64 + kk + 1) * 64 + n]);
        return (uint32_t)__half_as_ushort(h0) | ((uint32_t)__half_as_ushort(h1) << 16);
    };
    uint4 v;
    v.x = pack(kk0); v.y = pack(kk0 + 8); v.z = pack(kk0 + 16); v.w = pack(kk0 + 24);
    wf[idx] = v;
}

__global__ void prep_feats(const float* __restrict__ f, fp16* __restrict__ x16, int n) {
    int i = blockIdx.x * 256 + threadIdx.x;
    if (i >= n) return;
    x16[i] = __float2half(f[i]);
}

// ---------------- main conv kernel ----------------
// MODE 0: relu(acc+b) -> fp16 | MODE 1: (acc+b)*beta+gamma -> fp16 (extra=cond)
// MODE 3: relu(acc+b)+extra -> fp32 (extra=feats)
template <int MODE>
__global__ __launch_bounds__(256, 2) void conv_mma(
    const fp16* __restrict__ x,
    const int*  __restrict__ nbr,
    const uint4* __restrict__ wf,
    const float* __restrict__ bias, const float* __restrict__ extra,
    float* __restrict__ outf, fp16* __restrict__ out16,
    int P)
{
    extern __shared__ char smem[];
    const uint32_t sb = (uint32_t)__cvta_generic_to_shared(smem);
    const int tid  = threadIdx.x;
    const int wid  = tid >> 5;
    const int lane = tid & 31;
    const int wy   = wid >> 1;        // 0..3 : 32-row slab
    const int wx   = wid & 1;         // 0..1 : 32-col half
    const int rA   = lane >> 2;
    const int cq   = lane & 3;
    const int p0   = blockIdx.x * 128;

    // ---- per-lane neighbor indices (local memory; dynamic index in stage) ----
    const int myrow = wy * 32 + lane;
    const int myp   = p0 + myrow;
    int nloc[27];
    uint32_t rowtaps = 0;
    {
        const int* nrow = nbr + (size_t)myp * 27;
        #pragma unroll
        for (int k = 0; k < 27; ++k) {
            int n = (myp < P) ? __ldg(nrow + k) : -1;
            nloc[k] = n;
            rowtaps |= (n >= 0) ? (1u << k) : 0u;
        }
    }
    uint32_t wmask = rowtaps;
    #pragma unroll
    for (int o = 16; o; o >>= 1) wmask |= __shfl_xor_sync(0xffffffffu, wmask, o);

    float acc[2][4][4];
    #pragma unroll
    for (int t = 0; t < 2; ++t)
        #pragma unroll
        for (int j = 0; j < 4; ++j)
            #pragma unroll
            for (int q = 0; q < 4; ++q) acc[t][j][q] = 0.f;

    // ---- warp-private 3-buffer ring: zero fully once (12288B = 24 chunks/lane)
    char* wbuf0 = smem + wid * 12288;
    #pragma unroll
    for (int i = 0; i < 24; ++i)
        zero16(wbuf0 + (i * 32 + lane) * 16);

    uint32_t ten0 = 0u, ten1 = 0u, ten2 = 0u;   // non-zero rows per buffer
    uint32_t vm0 = 0u, vm1 = 0u, vm2 = 0u;      // staged tap's valid mask
    const uint32_t mybit = 1u << lane;

    auto stage_g = [&](int k, char* base, uint32_t& ten, uint32_t& vm) {
        const int n = (k >= 0) ? nloc[k] : -1;
        const uint32_t newm = __ballot_sync(0xffffffffu, n >= 0);
        char* dst = base + lane * 128;
        if (n >= 0) {
            const fp16* src = x + (size_t)n * 64;
            #pragma unroll
            for (int c = 0; c < 8; ++c)
                cp16b(dst + ((c ^ (lane & 7)) << 4), src + c * 8);
        } else if (k >= 0 && (ten & mybit)) {
            #pragma unroll
            for (int c = 0; c < 8; ++c)
                zero16(dst + (c << 4));
        }
        CP_COMMIT();
        if (k >= 0) { ten = newm; vm = newm; }
    };
    auto stage0 = [&](int k) { stage_g(k, wbuf0,         ten0, vm0); };
    auto stage1 = [&](int k) { stage_g(k, wbuf0 + 4096,  ten1, vm1); };
    auto stage2 = [&](int k) { stage_g(k, wbuf0 + 8192,  ten2, vm2); };

    // ldmatrix A mapping (warp-local rows 0..31)
    const int mm = lane >> 3;
    const int r8 = lane & 7;
    const int arow0 = (mm & 1) * 8 + r8;
    const int akc   = mm >> 1;

    const uint4* wbase = wf + ((size_t)wx * 8) * 32 + lane;

    auto compute = [&](int k, int buf, uint32_t vm) {
        const bool act0 = (vm & 0x0000FFFFu) != 0;
        const bool act1 = (vm & 0xFFFF0000u) != 0;
        const uint32_t stg = sb + (uint32_t)(wid * 12288 + buf * 4096);
        const uint4* wp = wbase + (size_t)k * 16 * 32;

        uint4 bv[8];                        // full-tap B burst (max MLP)
        #pragma unroll
        for (int i = 0; i < 8; ++i) bv[i] = wp[i * 32];

        #pragma unroll
        for (int kp = 0; kp < 2; ++kp) {
            #pragma unroll
            for (int par = 0; par < 2; ++par) {
                const int ca = (kp * 2 + par) * 2 + akc;
                uint32_t a[2][4];
                #pragma unroll
                for (int t = 0; t < 2; ++t) {
                    if (t == 0 ? act0 : act1) {
                        const int row = arow0 + t * 16;
                        const uint32_t off =
                            (uint32_t)(row * 128 + (((uint32_t)ca ^ (row & 7)) << 4));
                        ldsm4(a[t], stg + off);
                    }
                }
                #pragma unroll
                for (int t = 0; t < 2; ++t) {
                    if (t == 0 ? !act0 : !act1) continue;
                    #pragma unroll
                    for (int j = 0; j < 4; ++j) {
                        const uint4& b = bv[kp * 4 + j];
                        if (par == 0) mma_fp16(acc[t][j], a[t], b.x, b.y);
                        else          mma_fp16(acc[t][j], a[t], b.z, b.w);
                    }
                }
            }
        }
    };

    // ---- warp-autonomous mainloop, 3-slot static ring, stage 2 ahead ----
    {
        uint32_t m = wmask;
        auto nxt = [&]() -> int {
            if (!m) return -1;
            int k = __ffs(m) - 1; m &= m - 1; return k;
        };
        int ka = nxt(), kb = nxt(), kc = nxt();
        stage0(ka); stage1(kb); stage2(kc);
        while (ka >= 0) {
            CP_WAIT2(); __syncwarp();
            compute(ka, 0, vm0);
            int kd = nxt(); stage0(kd);
            CP_WAIT2(); __syncwarp();
            if (kb >= 0) compute(kb, 1, vm1);
            int ke = nxt(); stage1(ke);
            CP_WAIT2(); __syncwarp();
            if (kc >= 0) compute(kc, 2, vm2);
            int kf = nxt(); stage2(kf);
            ka = kd; kb = ke; kc = kf;
        }
        CP_WAIT0();
    }

    // ---------------- epilogue (bias via __ldg; no smem, no barriers) ----------
    float bb[8];
    #pragma unroll
    for (int j = 0; j < 4; ++j) {
        bb[j * 2 + 0] = __ldg(bias + wx * 32 + j * 8 + cq * 2);
        bb[j * 2 + 1] = __ldg(bias + wx * 32 + j * 8 + cq * 2 + 1);
    }
    #pragma unroll
    for (int t = 0; t < 2; ++t) {
        #pragma unroll
        for (int half = 0; half < 2; ++half) {
            const int p = p0 + wy * 32 + t * 16 + rA + half * 8;
            if (p >= P) continue;
            #pragma unroll
            for (int j = 0; j < 4; ++j) {
                const int col = wx * 32 + j * 8 + cq * 2;
                float v0 = acc[t][j][half * 2 + 0] + bb[j * 2 + 0];
                float v1 = acc[t][j][half * 2 + 1] + bb[j * 2 + 1];
                if (MODE == 0) {
                    v0 = fmaxf(v0, 0.f); v1 = fmaxf(v1, 0.f);
                } else if (MODE == 1) {
                    float2 be = *(const float2*)(extra + (size_t)p * 128 + col);
                    float2 ga = *(const float2*)(extra + (size_t)p * 128 + 64 + col);
                    v0 = v0 * be.x + ga.x;
                    v1 = v1 * be.y + ga.y;
                } else {
                    float2 rs = *(const float2*)(extra + (size_t)p * 64 + col);
                    v0 = fmaxf(v0, 0.f) + rs.x;
                    v1 = fmaxf(v1, 0.f) + rs.y;
                }
                if (MODE == 3) {
                    *(float2*)(outf + (size_t)p * 64 + col) = make_float2(v0, v1);
                } else {
                    __half2 hv = __floats2half2_rn(v0, v1);
                    *(__half2*)(out16 + (size_t)p * 64 + col) = hv;
                }
            }
        }
    }
}

// ---------------- launch ----------------
extern "C" void kernel_launch(void* const* d_in, const int* in_sizes, int n_in,
                              void* d_out, int out_size)
{
    const float* feats = (const float*)d_in[0];
    const float* cond  = (const float*)d_in[1];
    const float* W1a   = (const float*)d_in[2];
    const float* b1a   = (const float*)d_in[3];
    const float* W1b   = (const float*)d_in[4];
    const float* b1b   = (const float*)d_in[5];
    const float* W2a   = (const float*)d_in[6];
    const float* b2a   = (const float*)d_in[7];
    const float* W2b   = (const float*)d_in[8];
    const float* b2b   = (const float*)d_in[9];
    const int*   nbr   = (const int*)d_in[10];

    int P = in_sizes[0] / N_CH;
    float* out = (float*)d_out;

    fp16 *x16, *a16, *b16;
    uint4* wf;
    cudaGetSymbolAddress((void**)&x16, g_x16);
    cudaGetSymbolAddress((void**)&a16, g_a16);
    cudaGetSymbolAddress((void**)&b16, g_b16);
    cudaGetSymbolAddress((void**)&wf,  g_wf);

    cudaFuncSetAttribute(conv_mma<0>, cudaFuncAttributeMaxDynamicSharedMemorySize, SMEM_TOTAL);
    cudaFuncSetAttribute(conv_mma<1>, cudaFuncAttributeMaxDynamicSharedMemorySize, SMEM_TOTAL);
    cudaFuncSetAttribute(conv_mma<3>, cudaFuncAttributeMaxDynamicSharedMemorySize, SMEM_TOTAL);

    prep_weights<<<(4 * 27 * 16 * 32 + 255) / 256, 256>>>(W1a, W1b, W2a, W2b, wf);
    prep_feats<<<(P * N_CH + 255) / 256, 256>>>(feats, x16, P * N_CH);

    const size_t LW = (size_t)27 * 16 * 32;
    int grid = (P + 127) / 128;
    conv_mma<0><<<grid, 256, SMEM_TOTAL>>>(x16, nbr, wf + 0 * LW,
                                           b1a, nullptr, nullptr, a16, P);
    conv_mma<1><<<grid, 256, SMEM_TOTAL>>>(a16, nbr, wf + 1 * LW,
                                           b1b, cond, nullptr, b16, P);
    conv_mma<0><<<grid, 256, SMEM_TOTAL>>>(b16, nbr, wf + 2 * LW,
                                           b2a, nullptr, nullptr, a16, P);
    conv_mma<3><<<grid, 256, SMEM_TOTAL>>>(a16, nbr, wf + 3 * LW,
                                           b2b, feats, out, nullptr, P);
}